// round 1
// baseline (speedup 1.0000x reference)
#include <cuda_runtime.h>
#include <cuda_fp16.h>
#include <mma.h>

using namespace nvcuda;

// Problem constants
#define BATCH 8192
#define I_DIM 512
#define H_DIM 1024
#define D_DIM 8
#define G3H   3072          // 3*H
#define IP    576           // I padded by one 64-chunk (bias column at k=512)
#define HPAD  1088          // H padded by one 64-chunk (bias/ones column at k=1024)

// GEMM tiling
#define BM 64
#define BN 64
#define KC 64
#define LDS 72              // shared leading dim (halves), multiple of 8, padded

// ---------------- device scratch (allocation-free rule: __device__ globals) ----
__device__ __half g_x16[BATCH * IP];       // x padded with ones column   (9.4 MB)
__device__ __half g_h16[BATCH * HPAD];     // gamma*h padded with ones col (17.8 MB)
__device__ __half g_wih[G3H * IP];         // W_ih padded with bias_ih col (3.5 MB)
__device__ __half g_whh[G3H * HPAD];       // W_hh padded with bias_hh col (6.7 MB)

// ---------------- prep: fp32 -> fp16 with pad column -------------------------
// c < sc       : copy src
// c == sc      : bias[r] (or 1.0 if bias == nullptr, used for the activations)
// c > sc       : 0
__global__ void convert_pad_kernel(const float* __restrict__ src,
                                   const float* __restrict__ bias,
                                   __half* __restrict__ dst,
                                   int rows, int sc, int dc) {
    int total = rows * dc;
    for (int idx = blockIdx.x * blockDim.x + threadIdx.x; idx < total;
         idx += gridDim.x * blockDim.x) {
        int r = idx / dc;
        int c = idx - r * dc;
        float v;
        if (c < sc)       v = src[r * sc + c];
        else if (c == sc) v = bias ? bias[r] : 1.0f;
        else              v = 0.0f;
        dst[idx] = __float2half(v);
    }
}

// ---------------- prep: h' = exp(-relu(delta @ Wg^T + bg)) * h  -> fp16 ------
__global__ void gamma_h_kernel(const float* __restrict__ delta,
                               const float* __restrict__ h,
                               const float* __restrict__ wg,
                               const float* __restrict__ bg) {
    int total = BATCH * HPAD;
    for (int idx = blockIdx.x * blockDim.x + threadIdx.x; idx < total;
         idx += gridDim.x * blockDim.x) {
        int b = idx / HPAD;
        int j = idx - b * HPAD;
        float v;
        if (j < H_DIM) {
            const float4* d4 = reinterpret_cast<const float4*>(delta + b * D_DIM);
            const float4* w4 = reinterpret_cast<const float4*>(wg + j * D_DIM);
            float4 a0 = d4[0], a1 = d4[1];
            float4 w0 = w4[0], w1 = w4[1];
            float s = a0.x * w0.x + a0.y * w0.y + a0.z * w0.z + a0.w * w0.w
                    + a1.x * w1.x + a1.y * w1.y + a1.z * w1.z + a1.w * w1.w
                    + bg[j];
            float gmm = expf(-fmaxf(s, 0.0f));
            v = gmm * h[b * H_DIM + j];
        } else {
            v = (j == H_DIM) ? 1.0f : 0.0f;   // ones column for bias_hh folding
        }
        g_h16[idx] = __float2half(v);
    }
}

// ---------------- fused GEMM + GRU epilogue ----------------------------------
// Per 64x64 output tile, accumulate 7 GEMMs with identical fragment layouts:
//   acc[0..2]: i_r, i_z, i_n  (x  @ W_ih^T, K = IP,   bias folded in pad col)
//   acc[3..5]: h_r, h_z, h_n  (h' @ W_hh^T, K = HPAD, bias folded in pad col)
//   acc[6]   : h' itself via identity GEMM (same element mapping as gates)
// Epilogue is pure register math; result stored straight to d_out.
__global__ __launch_bounds__(256)
void grud_gemm_kernel(float* __restrict__ out) {
    __shared__ __align__(16) __half a_s[BM][LDS];
    __shared__ __align__(16) __half w_s[3][BN][LDS];

    const int tid   = threadIdx.x;
    const int wid   = tid >> 5;
    const int warpM = wid >> 1;      // 0..3  (16-row strip)
    const int warpN = wid & 1;       // 0..1  (32-col strip)
    const int bm = blockIdx.x * BM;  // batch base
    const int jb = blockIdx.y * BN;  // hidden-unit base

    wmma::fragment<wmma::accumulator, 16, 16, 16, float> acc[7][2];
#pragma unroll
    for (int g = 0; g < 7; g++)
#pragma unroll
        for (int nf = 0; nf < 2; nf++)
            wmma::fill_fragment(acc[g][nf], 0.0f);

    // ---- phase 1: gi = x @ W_ih^T (+bias via pad) ----
    for (int kc = 0; kc < IP; kc += KC) {
        __syncthreads();
#pragma unroll
        for (int u = tid; u < 512; u += 256) {           // A tile: 64x64 halves
            int r = u >> 3, c8 = u & 7;
            reinterpret_cast<int4*>(&a_s[r][0])[c8] =
                *reinterpret_cast<const int4*>(&g_x16[(bm + r) * IP + kc + c8 * 8]);
        }
#pragma unroll
        for (int u = tid; u < 1536; u += 256) {          // 3 weight tiles
            int g = u >> 9, rem = u & 511;
            int n = rem >> 3, c8 = rem & 7;
            reinterpret_cast<int4*>(&w_s[g][n][0])[c8] =
                *reinterpret_cast<const int4*>(
                    &g_wih[(jb + n + g * H_DIM) * IP + kc + c8 * 8]);
        }
        __syncthreads();
#pragma unroll
        for (int kk = 0; kk < KC; kk += 16) {
            wmma::fragment<wmma::matrix_a, 16, 16, 16, __half, wmma::row_major> af;
            wmma::load_matrix_sync(af, &a_s[warpM * 16][kk], LDS);
#pragma unroll
            for (int g = 0; g < 3; g++) {
#pragma unroll
                for (int nf = 0; nf < 2; nf++) {
                    wmma::fragment<wmma::matrix_b, 16, 16, 16, __half, wmma::col_major> bf;
                    wmma::load_matrix_sync(bf, &w_s[g][warpN * 32 + nf * 16][kk], LDS);
                    wmma::mma_sync(acc[g][nf], af, bf, acc[g][nf]);
                }
            }
        }
    }

    // ---- phase 2: gh = h' @ W_hh^T (+bias via pad) ----
    for (int kc = 0; kc < HPAD; kc += KC) {
        __syncthreads();
#pragma unroll
        for (int u = tid; u < 512; u += 256) {
            int r = u >> 3, c8 = u & 7;
            reinterpret_cast<int4*>(&a_s[r][0])[c8] =
                *reinterpret_cast<const int4*>(&g_h16[(bm + r) * HPAD + kc + c8 * 8]);
        }
#pragma unroll
        for (int u = tid; u < 1536; u += 256) {
            int g = u >> 9, rem = u & 511;
            int n = rem >> 3, c8 = rem & 7;
            reinterpret_cast<int4*>(&w_s[g][n][0])[c8] =
                *reinterpret_cast<const int4*>(
                    &g_whh[(jb + n + g * H_DIM) * HPAD + kc + c8 * 8]);
        }
        __syncthreads();
#pragma unroll
        for (int kk = 0; kk < KC; kk += 16) {
            wmma::fragment<wmma::matrix_a, 16, 16, 16, __half, wmma::row_major> af;
            wmma::load_matrix_sync(af, &a_s[warpM * 16][kk], LDS);
#pragma unroll
            for (int g = 0; g < 3; g++) {
#pragma unroll
                for (int nf = 0; nf < 2; nf++) {
                    wmma::fragment<wmma::matrix_b, 16, 16, 16, __half, wmma::col_major> bf;
                    wmma::load_matrix_sync(bf, &w_s[g][warpN * 32 + nf * 16][kk], LDS);
                    wmma::mma_sync(acc[3 + g][nf], af, bf, acc[3 + g][nf]);
                }
            }
        }
    }

    // ---- phase 3: h' tile via identity GEMM (gets fragment-compatible layout)
    __syncthreads();
#pragma unroll
    for (int u = tid; u < 512; u += 256) {               // A = h'[:, jb:jb+64]
        int r = u >> 3, c8 = u & 7;
        reinterpret_cast<int4*>(&a_s[r][0])[c8] =
            *reinterpret_cast<const int4*>(&g_h16[(bm + r) * HPAD + jb + c8 * 8]);
    }
#pragma unroll
    for (int u = tid; u < 4096; u += 256) {              // B = I_64 in w_s[0]
        int n = u >> 6, k = u & 63;
        w_s[0][n][k] = __float2half(n == k ? 1.0f : 0.0f);
    }
    __syncthreads();
#pragma unroll
    for (int kk = 0; kk < KC; kk += 16) {
        wmma::fragment<wmma::matrix_a, 16, 16, 16, __half, wmma::row_major> af;
        wmma::load_matrix_sync(af, &a_s[warpM * 16][kk], LDS);
#pragma unroll
        for (int nf = 0; nf < 2; nf++) {
            wmma::fragment<wmma::matrix_b, 16, 16, 16, __half, wmma::col_major> bf;
            wmma::load_matrix_sync(bf, &w_s[0][warpN * 32 + nf * 16][kk], LDS);
            wmma::mma_sync(acc[6][nf], af, bf, acc[6][nf]);
        }
    }

    // ---- epilogue: all accumulators share element layout -> register math ----
#pragma unroll
    for (int nf = 0; nf < 2; nf++) {
        wmma::fragment<wmma::accumulator, 16, 16, 16, float> res;
#pragma unroll
        for (int e = 0; e < 8; e++) {
            float rp = acc[0][nf].x[e] + acc[3][nf].x[e];   // i_r + h_r (biases folded)
            float zp = acc[1][nf].x[e] + acc[4][nf].x[e];   // i_z + h_z
            float r  = 1.0f / (1.0f + expf(-rp));
            float z  = 1.0f / (1.0f + expf(-zp));
            float n  = tanhf(acc[2][nf].x[e] + r * acc[5][nf].x[e]);
            float hh = acc[6][nf].x[e];                     // h' (decayed hidden)
            res.x[e] = n + z * (hh - n);
        }
        wmma::store_matrix_sync(
            &out[(bm + warpM * 16) * H_DIM + jb + warpN * 32 + nf * 16],
            res, H_DIM, wmma::mem_row_major);
    }
}

// ---------------- launch ------------------------------------------------------
extern "C" void kernel_launch(void* const* d_in, const int* in_sizes, int n_in,
                              void* d_out, int out_size) {
    const float* x         = (const float*)d_in[0];   // [B, I]
    const float* delta     = (const float*)d_in[1];   // [B, D]
    const float* h         = (const float*)d_in[2];   // [B, H]
    const float* weight_ih = (const float*)d_in[3];   // [3H, I]
    const float* weight_hh = (const float*)d_in[4];   // [3H, H]
    const float* bias_ih   = (const float*)d_in[5];   // [3H]
    const float* bias_hh   = (const float*)d_in[6];   // [3H]
    const float* w_gamma   = (const float*)d_in[7];   // [H, D]
    const float* b_gamma   = (const float*)d_in[8];   // [H]
    float* out = (float*)d_out;                       // [B, H]

    const int T = 256;
    __half* dx; cudaGetSymbolAddress((void**)&dx, g_x16);
    __half* dwih; cudaGetSymbolAddress((void**)&dwih, g_wih);
    __half* dwhh; cudaGetSymbolAddress((void**)&dwhh, g_whh);

    // x -> fp16 with ones column
    {
        int total = BATCH * IP;
        convert_pad_kernel<<<(total + T - 1) / T, T>>>(x, nullptr, dx, BATCH, I_DIM, IP);
    }
    // W_ih -> fp16 with bias_ih column
    {
        int total = G3H * IP;
        convert_pad_kernel<<<(total + T - 1) / T, T>>>(weight_ih, bias_ih, dwih, G3H, I_DIM, IP);
    }
    // W_hh -> fp16 with bias_hh column
    {
        int total = G3H * HPAD;
        convert_pad_kernel<<<(total + T - 1) / T, T>>>(weight_hh, bias_hh, dwhh, G3H, H_DIM, HPAD);
    }
    // h' = gamma * h  -> fp16 with ones column
    {
        int total = BATCH * HPAD;
        gamma_h_kernel<<<(total + T - 1) / T, T>>>(delta, h, w_gamma, b_gamma);
    }
    // fused GEMMs + GRU epilogue
    {
        dim3 grid(BATCH / BM, H_DIM / BN);
        grud_gemm_kernel<<<grid, 256>>>(out);
    }
}

// round 4
// speedup vs baseline: 1.4510x; 1.4510x over previous
#include <cuda_runtime.h>
#include <cuda_fp16.h>
#include <cstdint>

// ---------------- problem constants ------------------------------------------
#define BATCH 8192
#define I_DIM 512
#define H_DIM 1024
#define D_DIM 8
#define G3H   3072
#define IP    576            // I + 64 pad (bias column at k=512)
#define HPAD  1088           // H + 64 pad (bias/ones column at k=1024)

// ---------------- GEMM tiling ------------------------------------------------
#define BM 256               // batch rows per CTA
#define BN 32                // hidden cols per CTA (per gate; 3 gates computed)
#define KC 64                // halves per K-chunk
#define NCHUNK1 9            // 576/64   (x @ W_ih^T)
#define NCHUNKS 26           // + 1088/64 (h' @ W_hh^T)
#define NSTAGE 3
#define SPITCH 144           // bytes per SMEM row (64 halves + 8 pad) -> conflict-free
#define SROWS (BM + 3 * BN)  // 256 A rows + 96 B rows = 352
#define STAGE_BYTES (SROWS * SPITCH)            // 50688
#define SMEM_ALLOC (NSTAGE * STAGE_BYTES + 256)

// ---------------- device scratch ---------------------------------------------
__device__ __half g_x16[BATCH * IP];
__device__ __half g_h16[BATCH * HPAD];
__device__ __half g_wih[G3H * IP];
__device__ __half g_whh[G3H * HPAD];

// ---------------- PTX helpers ------------------------------------------------
__device__ __forceinline__ uint32_t smem_u32(const void* p) {
    uint32_t a;
    asm("{ .reg .u64 t; cvta.to.shared.u64 t, %1; cvt.u32.u64 %0, t; }"
        : "=r"(a) : "l"(p));
    return a;
}
__device__ __forceinline__ void cp16(uint32_t dst, const void* src) {
    asm volatile("cp.async.cg.shared.global [%0], [%1], 16;" :: "r"(dst), "l"(src));
}
#define CP_COMMIT() asm volatile("cp.async.commit_group;" ::: "memory")
#define CP_WAIT(n)  asm volatile("cp.async.wait_group %0;" :: "n"(n) : "memory")

// ---------------- prep: fp32 -> fp16 with pad column (vectorized x4) ---------
__global__ void convert_pad4(const float* __restrict__ src,
                             const float* __restrict__ bias,
                             __half* __restrict__ dst,
                             int rows, int sc, int dc) {
    int q = dc >> 2;
    int total = rows * q;
    for (int idx = blockIdx.x * blockDim.x + threadIdx.x; idx < total;
         idx += gridDim.x * blockDim.x) {
        int r = idx / q, cq = idx - r * q, c0 = cq << 2;
        float v[4];
        if (c0 + 3 < sc) {
            float4 f = *reinterpret_cast<const float4*>(src + (size_t)r * sc + c0);
            v[0] = f.x; v[1] = f.y; v[2] = f.z; v[3] = f.w;
        } else {
#pragma unroll
            for (int k = 0; k < 4; k++) {
                int c = c0 + k;
                v[k] = (c < sc) ? src[(size_t)r * sc + c]
                                : ((c == sc) ? (bias ? bias[r] : 1.0f) : 0.0f);
            }
        }
        __half h4[4];
#pragma unroll
        for (int k = 0; k < 4; k++) h4[k] = __float2half(v[k]);
        *reinterpret_cast<uint2*>(dst + (size_t)r * dc + c0) =
            *reinterpret_cast<uint2*>(h4);
    }
}

// ---------------- prep: h' = exp(-relu(delta @ Wg^T + bg)) * h ---------------
__global__ void gamma_h_kernel(const float* __restrict__ delta,
                               const float* __restrict__ h,
                               const float* __restrict__ wg,
                               const float* __restrict__ bg) {
    int b = blockIdx.x;
    const float4* d4 = reinterpret_cast<const float4*>(delta + (size_t)b * D_DIM);
    float4 a0 = d4[0], a1 = d4[1];
    int t = threadIdx.x;                         // 256 threads
    int j0 = t * 4;
    float4 hv = *reinterpret_cast<const float4*>(h + (size_t)b * H_DIM + j0);
    __half o4[4];
#pragma unroll
    for (int k = 0; k < 4; k++) {
        int j = j0 + k;
        const float4* w4 = reinterpret_cast<const float4*>(wg + (size_t)j * D_DIM);
        float4 w0 = w4[0], w1 = w4[1];
        float s = a0.x * w0.x + a0.y * w0.y + a0.z * w0.z + a0.w * w0.w
                + a1.x * w1.x + a1.y * w1.y + a1.z * w1.z + a1.w * w1.w + bg[j];
        float g = __expf(-fmaxf(s, 0.0f));
        o4[k] = __float2half(g * (&hv.x)[k]);
    }
    *reinterpret_cast<uint2*>(g_h16 + (size_t)b * HPAD + j0) =
        *reinterpret_cast<uint2*>(o4);
    if (t < 16) {                                // pad cols 1024..1087
        int j = 1024 + t * 4;
        __half p4[4];
#pragma unroll
        for (int k = 0; k < 4; k++) p4[k] = __float2half((j + k) == 1024 ? 1.0f : 0.0f);
        *reinterpret_cast<uint2*>(g_h16 + (size_t)b * HPAD + j) =
            *reinterpret_cast<uint2*>(p4);
    }
}

// ---------------- chunk loader (cp.async, 2816 x 16B per chunk) --------------
// 352 rows x 128 bytes  =  2816 16B transfers  =  11 iterations x 256 threads
__device__ __forceinline__ void load_chunk(uint32_t stage_sb, int c,
                                           int bm, int jb, int tid) {
    const __half* A; const __half* B; int ld_; int kc;
    if (c < NCHUNK1) { A = g_x16; B = g_wih; ld_ = IP;   kc = c * KC; }
    else             { A = g_h16; B = g_whh; ld_ = HPAD; kc = (c - NCHUNK1) * KC; }
#pragma unroll
    for (int i = 0; i < 11; i++) {
        int u = tid + i * 256;                   // 0..2815
        int row = u >> 3, cc = u & 7;            // 8 x 16B per row
        const __half* src;
        if (row < BM) {
            src = A + (size_t)(bm + row) * ld_ + kc + cc * 8;
        } else {
            int rr = row - BM;                   // 0..95
            int g = rr >> 5, n = rr & 31;
            src = B + (size_t)(jb + n + g * H_DIM) * ld_ + kc + cc * 8;
        }
        cp16(stage_sb + (uint32_t)(row * SPITCH + cc * 16), src);
    }
    CP_COMMIT();
}

// ---------------- per-chunk MMA: 4 k-steps, 3 gates, slot-templated ----------
// acc slots: 0 = r_pre (both phases), 1 = z_pre (both), 2 = i_n, 3 = h_n
template <int SN>
__device__ __forceinline__ void mma_chunk(float (&acc)[4][2][4][4],
                                          const char* stage,
                                          int wrow, int gid, int tig) {
    const char* As = stage;
    const char* Bs = stage + BM * SPITCH;
#pragma unroll
    for (int ks = 0; ks < 4; ks++) {
        const int k0 = ks * 16;
        uint32_t a[2][4];
#pragma unroll
        for (int m = 0; m < 2; m++) {
            const int rb = wrow + m * 16;
            a[m][0] = *(const uint32_t*)(As + (rb + gid)     * SPITCH + (k0 + tig * 2)     * 2);
            a[m][1] = *(const uint32_t*)(As + (rb + gid + 8) * SPITCH + (k0 + tig * 2)     * 2);
            a[m][2] = *(const uint32_t*)(As + (rb + gid)     * SPITCH + (k0 + tig * 2 + 8) * 2);
            a[m][3] = *(const uint32_t*)(As + (rb + gid + 8) * SPITCH + (k0 + tig * 2 + 8) * 2);
        }
#pragma unroll
        for (int g = 0; g < 3; g++) {
            const int slot = (g == 0) ? 0 : (g == 1) ? 1 : SN;
#pragma unroll
            for (int n = 0; n < 4; n++) {
                const char* bp = Bs + (g * 32 + n * 8 + gid) * SPITCH;
                uint32_t b0 = *(const uint32_t*)(bp + (k0 + tig * 2)     * 2);
                uint32_t b1 = *(const uint32_t*)(bp + (k0 + tig * 2 + 8) * 2);
#pragma unroll
                for (int m = 0; m < 2; m++) {
                    asm volatile(
                        "mma.sync.aligned.m16n8k16.row.col.f32.f16.f16.f32 "
                        "{%0,%1,%2,%3}, {%4,%5,%6,%7}, {%8,%9}, {%0,%1,%2,%3};"
                        : "+f"(acc[slot][m][n][0]), "+f"(acc[slot][m][n][1]),
                          "+f"(acc[slot][m][n][2]), "+f"(acc[slot][m][n][3])
                        : "r"(a[m][0]), "r"(a[m][1]), "r"(a[m][2]), "r"(a[m][3]),
                          "r"(b0), "r"(b1));
                }
            }
        }
    }
}

// ---------------- main GEMM + GRU epilogue -----------------------------------
__global__ void __launch_bounds__(256, 1)
grud_mma_kernel(float* __restrict__ out) {
    extern __shared__ char smem_raw[];
    const uint32_t sb = (smem_u32(smem_raw) + 127) & ~127u;
    char* sp = (char*)(smem_raw + (sb - smem_u32(smem_raw)));

    const int tid = threadIdx.x;
    const int wid = tid >> 5, lid = tid & 31;
    const int gid = lid >> 2, tig = lid & 3;      // groupID / thread-in-group
    const int wrow = wid * 32;                    // warp's 32-row strip in BM
    const int bm = blockIdx.x * BM, jb = blockIdx.y * BN;

    float acc[4][2][4][4];
#pragma unroll
    for (int s = 0; s < 4; s++)
#pragma unroll
        for (int m = 0; m < 2; m++)
#pragma unroll
            for (int n = 0; n < 4; n++)
#pragma unroll
                for (int e = 0; e < 4; e++) acc[s][m][n][e] = 0.0f;

    // prologue: fill 3 stages
    for (int c = 0; c < NSTAGE; c++)
        load_chunk(sb + c * STAGE_BYTES, c, bm, jb, tid);

#pragma unroll 1
    for (int c = 0; c < NCHUNKS; c++) {
        const int st = c % NSTAGE;
        if (c < NCHUNKS - 2)       CP_WAIT(2);
        else if (c == NCHUNKS - 2) CP_WAIT(1);
        else                       CP_WAIT(0);
        __syncthreads();

        const char* stage = sp + st * STAGE_BYTES;
        if (c < NCHUNK1) mma_chunk<2>(acc, stage, wrow, gid, tig);
        else             mma_chunk<3>(acc, stage, wrow, gid, tig);

        __syncthreads();
        if (c + NSTAGE < NCHUNKS)
            load_chunk(sb + st * STAGE_BYTES, c + NSTAGE, bm, jb, tid);
    }

    // ---- epilogue: GRU math straight from registers -------------------------
#pragma unroll
    for (int m = 0; m < 2; m++) {
        const int r0 = bm + wrow + m * 16 + gid;  // rows r0 and r0+8
#pragma unroll
        for (int n = 0; n < 4; n++) {
            const int col = jb + n * 8 + tig * 2;
            __half2 ha = *(const __half2*)(g_h16 + (size_t)r0 * HPAD + col);
            __half2 hb = *(const __half2*)(g_h16 + (size_t)(r0 + 8) * HPAD + col);
            float h0 = __half2float(ha.x), h1 = __half2float(ha.y);
            float h2 = __half2float(hb.x), h3 = __half2float(hb.y);
            float o[4];
#pragma unroll
            for (int e = 0; e < 4; e++) {
                float r  = 1.0f / (1.0f + __expf(-acc[0][m][n][e]));
                float z  = 1.0f / (1.0f + __expf(-acc[1][m][n][e]));
                float na = acc[2][m][n][e] + r * acc[3][m][n][e];
                float nn = 2.0f / (1.0f + __expf(-2.0f * na)) - 1.0f;   // tanh
                float hq = (e == 0) ? h0 : (e == 1) ? h1 : (e == 2) ? h2 : h3;
                o[e] = nn + z * (hq - nn);
            }
            *(float2*)(out + (size_t)r0 * H_DIM + col)       = make_float2(o[0], o[1]);
            *(float2*)(out + (size_t)(r0 + 8) * H_DIM + col) = make_float2(o[2], o[3]);
        }
    }
}

// ---------------- launch ------------------------------------------------------
extern "C" void kernel_launch(void* const* d_in, const int* in_sizes, int n_in,
                              void* d_out, int out_size) {
    const float* x         = (const float*)d_in[0];
    const float* delta     = (const float*)d_in[1];
    const float* h         = (const float*)d_in[2];
    const float* weight_ih = (const float*)d_in[3];
    const float* weight_hh = (const float*)d_in[4];
    const float* bias_ih   = (const float*)d_in[5];
    const float* bias_hh   = (const float*)d_in[6];
    const float* w_gamma   = (const float*)d_in[7];
    const float* b_gamma   = (const float*)d_in[8];
    float* out = (float*)d_out;

    __half* dx;   cudaGetSymbolAddress((void**)&dx,   g_x16);
    __half* dwih; cudaGetSymbolAddress((void**)&dwih, g_wih);
    __half* dwhh; cudaGetSymbolAddress((void**)&dwhh, g_whh);

    cudaFuncSetAttribute(grud_mma_kernel,
                         cudaFuncAttributeMaxDynamicSharedMemorySize, SMEM_ALLOC);

    const int T = 256;
    { int tot = BATCH * IP / 4;  convert_pad4<<<(tot + T - 1) / T, T>>>(x, nullptr, dx, BATCH, I_DIM, IP); }
    { int tot = G3H * IP / 4;    convert_pad4<<<(tot + T - 1) / T, T>>>(weight_ih, bias_ih, dwih, G3H, I_DIM, IP); }
    { int tot = G3H * HPAD / 4;  convert_pad4<<<(tot + T - 1) / T, T>>>(weight_hh, bias_hh, dwhh, G3H, H_DIM, HPAD); }
    gamma_h_kernel<<<BATCH, 256>>>(delta, h, w_gamma, b_gamma);

    dim3 grid(BATCH / BM, H_DIM / BN);   // (32, 32)
    grud_mma_kernel<<<grid, 256, SMEM_ALLOC>>>(out);
}

// round 5
// speedup vs baseline: 1.6124x; 1.1112x over previous
#include <cuda_runtime.h>
#include <cuda_fp16.h>
#include <cstdint>

// ---------------- problem constants ------------------------------------------
#define BATCH 8192
#define I_DIM 512
#define H_DIM 1024
#define D_DIM 8
#define G3H   3072
#define IP    576            // I + 64 pad (bias column at k=512)
#define HPAD  1088           // H + 64 pad (bias/ones column at k=1024)

// ---------------- GEMM tiling ------------------------------------------------
#define BM 128               // batch rows per CTA
#define BN 32                // hidden cols per CTA (per gate; 3 gates computed)
#define KC 64                // halves per K-chunk
#define NCHUNK1 9            // 576/64   (x @ W_ih^T)
#define NCHUNKS 26           // + 1088/64 (h' @ W_hh^T)
#define NSTAGE 3
#define SPITCH 144           // bytes per SMEM row (64 halves + 8 pad) -> conflict-free
#define SROWS (BM + 3 * BN)  // 128 A rows + 96 B rows = 224
#define STAGE_BYTES (SROWS * SPITCH)            // 32256
#define SMEM_ALLOC (NSTAGE * STAGE_BYTES + 256) // ~97KB -> 2 CTAs/SM

// ---------------- device scratch ---------------------------------------------
__device__ __half g_x16[BATCH * IP];
__device__ __half g_h16[BATCH * HPAD];
__device__ __half g_wih[G3H * IP];
__device__ __half g_whh[G3H * HPAD];

// ---------------- PTX helpers ------------------------------------------------
__device__ __forceinline__ uint32_t smem_u32(const void* p) {
    uint32_t a;
    asm("{ .reg .u64 t; cvta.to.shared.u64 t, %1; cvt.u32.u64 %0, t; }"
        : "=r"(a) : "l"(p));
    return a;
}
__device__ __forceinline__ void cp16(uint32_t dst, const void* src) {
    asm volatile("cp.async.cg.shared.global [%0], [%1], 16;" :: "r"(dst), "l"(src));
}
#define CP_COMMIT() asm volatile("cp.async.commit_group;" ::: "memory")
#define CP_WAIT(n)  asm volatile("cp.async.wait_group %0;" :: "n"(n) : "memory")
#define LDSM4(r0, r1, r2, r3, addr) \
    asm volatile("ldmatrix.sync.aligned.m8n8.x4.shared.b16 {%0,%1,%2,%3}, [%4];" \
        : "=r"(r0), "=r"(r1), "=r"(r2), "=r"(r3) : "r"(addr))

// ---------------- prep: fp32 -> fp16 with pad column (vectorized x4) ---------
__global__ void convert_pad4(const float* __restrict__ src,
                             const float* __restrict__ bias,
                             __half* __restrict__ dst,
                             int rows, int sc, int dc) {
    int q = dc >> 2;
    int total = rows * q;
    for (int idx = blockIdx.x * blockDim.x + threadIdx.x; idx < total;
         idx += gridDim.x * blockDim.x) {
        int r = idx / q, cq = idx - r * q, c0 = cq << 2;
        float v[4];
        if (c0 + 3 < sc) {
            float4 f = *reinterpret_cast<const float4*>(src + (size_t)r * sc + c0);
            v[0] = f.x; v[1] = f.y; v[2] = f.z; v[3] = f.w;
        } else {
#pragma unroll
            for (int k = 0; k < 4; k++) {
                int c = c0 + k;
                v[k] = (c < sc) ? src[(size_t)r * sc + c]
                                : ((c == sc) ? (bias ? bias[r] : 1.0f) : 0.0f);
            }
        }
        __half h4[4];
#pragma unroll
        for (int k = 0; k < 4; k++) h4[k] = __float2half(v[k]);
        *reinterpret_cast<uint2*>(dst + (size_t)r * dc + c0) =
            *reinterpret_cast<uint2*>(h4);
    }
}

// ---------------- prep: h' = exp(-relu(delta @ Wg^T + bg)) * h ---------------
// thread owns 4 fixed hidden units; w_gamma rows live in registers across the
// batch-row loop (w_gamma traffic: 262MB -> 4MB vs round 4)
#define GH_ROWS 64
__global__ void __launch_bounds__(256)
gamma_h_kernel(const float* __restrict__ delta,
               const float* __restrict__ h,
               const float* __restrict__ wg,
               const float* __restrict__ bg) {
    const int t = threadIdx.x;
    const int j0 = t * 4;                       // 4 hidden units per thread
    float w[4][8], b4[4];
#pragma unroll
    for (int k = 0; k < 4; k++) {
        const float4* w4 = reinterpret_cast<const float4*>(wg + (size_t)(j0 + k) * D_DIM);
        float4 lo = w4[0], hi = w4[1];
        w[k][0] = lo.x; w[k][1] = lo.y; w[k][2] = lo.z; w[k][3] = lo.w;
        w[k][4] = hi.x; w[k][5] = hi.y; w[k][6] = hi.z; w[k][7] = hi.w;
        b4[k] = bg[j0 + k];
    }
    const int r0 = blockIdx.x * GH_ROWS;
#pragma unroll 1
    for (int b = r0; b < r0 + GH_ROWS; b++) {
        const float4* d4 = reinterpret_cast<const float4*>(delta + (size_t)b * D_DIM);
        float4 a0 = d4[0], a1 = d4[1];          // uniform -> L1 broadcast
        float4 hv = *reinterpret_cast<const float4*>(h + (size_t)b * H_DIM + j0);
        __half o4[4];
#pragma unroll
        for (int k = 0; k < 4; k++) {
            float s = a0.x * w[k][0] + a0.y * w[k][1] + a0.z * w[k][2] + a0.w * w[k][3]
                    + a1.x * w[k][4] + a1.y * w[k][5] + a1.z * w[k][6] + a1.w * w[k][7]
                    + b4[k];
            float g = __expf(-fmaxf(s, 0.0f));
            o4[k] = __float2half(g * (&hv.x)[k]);
        }
        *reinterpret_cast<uint2*>(g_h16 + (size_t)b * HPAD + j0) =
            *reinterpret_cast<uint2*>(o4);
        if (t < 16) {                            // pad cols 1024..1087
            int j = 1024 + t * 4;
            __half p4[4];
#pragma unroll
            for (int k = 0; k < 4; k++) p4[k] = __float2half((j + k) == 1024 ? 1.0f : 0.0f);
            *reinterpret_cast<uint2*>(g_h16 + (size_t)b * HPAD + j) =
                *reinterpret_cast<uint2*>(p4);
        }
    }
}

// ---------------- chunk loader (cp.async, 1792 x 16B = 7 x 256) --------------
__device__ __forceinline__ void load_chunk(uint32_t stage_sb, int c,
                                           int bm, int jb, int tid) {
    const __half* A; const __half* B; int ld_; int kc;
    if (c < NCHUNK1) { A = g_x16; B = g_wih; ld_ = IP;   kc = c * KC; }
    else             { A = g_h16; B = g_whh; ld_ = HPAD; kc = (c - NCHUNK1) * KC; }
#pragma unroll
    for (int i = 0; i < 7; i++) {
        int u = tid + i * 256;                   // 0..1791
        int row = u >> 3, cc = u & 7;            // 8 x 16B per 128B row
        const __half* src;
        if (row < BM) {
            src = A + (size_t)(bm + row) * ld_ + kc + cc * 8;
        } else {
            int rr = row - BM;                   // 0..95
            int g = rr >> 5, n = rr & 31;
            src = B + (size_t)(jb + n + g * H_DIM) * ld_ + kc + cc * 8;
        }
        cp16(stage_sb + (uint32_t)(row * SPITCH + cc * 16), src);
    }
    CP_COMMIT();
}

// ---------------- per-chunk MMA: ldmatrix-fed, 4 k-steps, 3 gates ------------
// acc slots: 0 = r_pre (both phases), 1 = z_pre (both), 2 = i_n, 3 = h_n
// aoff: per-lane A ldmatrix base offset (within stage), boff: per-lane B base
template <int SN>
__device__ __forceinline__ void mma_chunk(float (&acc)[4][4][4],
                                          uint32_t stage_sb,
                                          uint32_t aoff, uint32_t boff) {
#pragma unroll
    for (int ks = 0; ks < 4; ks++) {
        const uint32_t kb = ks * 32;             // k0*2 bytes
        uint32_t a0, a1, a2, a3;
        LDSM4(a0, a1, a2, a3, stage_sb + aoff + kb);
#pragma unroll
        for (int g = 0; g < 3; g++) {
            const int slot = (g == 0) ? 0 : (g == 1) ? 1 : SN;
#pragma unroll
            for (int q = 0; q < 2; q++) {        // n-quads: n 0-15, n 16-31
                uint32_t b0, b1, b2, b3;
                LDSM4(b0, b1, b2, b3,
                      stage_sb + boff + (uint32_t)((g * 32 + q * 16) * SPITCH) + kb);
                asm volatile(
                    "mma.sync.aligned.m16n8k16.row.col.f32.f16.f16.f32 "
                    "{%0,%1,%2,%3}, {%4,%5,%6,%7}, {%8,%9}, {%0,%1,%2,%3};"
                    : "+f"(acc[slot][q * 2][0]), "+f"(acc[slot][q * 2][1]),
                      "+f"(acc[slot][q * 2][2]), "+f"(acc[slot][q * 2][3])
                    : "r"(a0), "r"(a1), "r"(a2), "r"(a3), "r"(b0), "r"(b1));
                asm volatile(
                    "mma.sync.aligned.m16n8k16.row.col.f32.f16.f16.f32 "
                    "{%0,%1,%2,%3}, {%4,%5,%6,%7}, {%8,%9}, {%0,%1,%2,%3};"
                    : "+f"(acc[slot][q * 2 + 1][0]), "+f"(acc[slot][q * 2 + 1][1]),
                      "+f"(acc[slot][q * 2 + 1][2]), "+f"(acc[slot][q * 2 + 1][3])
                    : "r"(a0), "r"(a1), "r"(a2), "r"(a3), "r"(b2), "r"(b3));
            }
        }
    }
}

// ---------------- main GEMM + GRU epilogue -----------------------------------
__global__ void __launch_bounds__(256, 2)
grud_mma_kernel(float* __restrict__ out) {
    extern __shared__ char smem_raw[];
    const uint32_t sb = (smem_u32(smem_raw) + 127) & ~127u;

    const int tid = threadIdx.x;
    const int wid = tid >> 5, lid = tid & 31;
    const int gid = lid >> 2, tig = lid & 3;      // groupID / thread-in-group
    const int wrow = wid * 16;                    // warp's 16-row strip in BM
    const int bm = blockIdx.x * BM, jb = blockIdx.y * BN;

    // ldmatrix per-lane offsets (t = lane/8 selects the 8x8 tile, ri = lane%8)
    const int t8 = lid >> 3, ri = lid & 7;
    // A x4 tiles: {rows@k0, rows+8@k0, rows@k0+8, rows+8@k0+8}
    const uint32_t aoff = (uint32_t)((wrow + (t8 & 1) * 8 + ri) * SPITCH + (t8 >> 1) * 16);
    // B x4 tiles: {n0-7@k0, n0-7@k0+8, n8-15@k0, n8-15@k0+8}
    const uint32_t boff = (uint32_t)((BM + (t8 >> 1) * 8 + ri) * SPITCH + (t8 & 1) * 16);

    float acc[4][4][4];
#pragma unroll
    for (int s = 0; s < 4; s++)
#pragma unroll
        for (int n = 0; n < 4; n++)
#pragma unroll
            for (int e = 0; e < 4; e++) acc[s][n][e] = 0.0f;

    // prologue: fill 3 stages
    for (int c = 0; c < NSTAGE; c++)
        load_chunk(sb + c * STAGE_BYTES, c, bm, jb, tid);

#pragma unroll 1
    for (int c = 0; c < NCHUNKS; c++) {
        const int st = c % NSTAGE;
        if (c < NCHUNKS - 2)       CP_WAIT(2);
        else if (c == NCHUNKS - 2) CP_WAIT(1);
        else                       CP_WAIT(0);
        __syncthreads();

        const uint32_t stage_sb = sb + st * STAGE_BYTES;
        if (c < NCHUNK1) mma_chunk<2>(acc, stage_sb, aoff, boff);
        else             mma_chunk<3>(acc, stage_sb, aoff, boff);

        __syncthreads();
        if (c + NSTAGE < NCHUNKS)
            load_chunk(sb + st * STAGE_BYTES, c + NSTAGE, bm, jb, tid);
    }

    // ---- epilogue: GRU math straight from registers -------------------------
    const int r0 = bm + wrow + gid;               // rows r0 and r0+8
#pragma unroll
    for (int n = 0; n < 4; n++) {
        const int col = jb + n * 8 + tig * 2;
        __half2 ha = *(const __half2*)(g_h16 + (size_t)r0 * HPAD + col);
        __half2 hb = *(const __half2*)(g_h16 + (size_t)(r0 + 8) * HPAD + col);
        float hq[4] = { __half2float(ha.x), __half2float(ha.y),
                        __half2float(hb.x), __half2float(hb.y) };
        float o[4];
#pragma unroll
        for (int e = 0; e < 4; e++) {
            float r  = 1.0f / (1.0f + __expf(-acc[0][n][e]));
            float z  = 1.0f / (1.0f + __expf(-acc[1][n][e]));
            float na = acc[2][n][e] + r * acc[3][n][e];
            float nn = 2.0f / (1.0f + __expf(-2.0f * na)) - 1.0f;   // tanh
            o[e] = nn + z * (hq[e] - nn);
        }
        *(float2*)(out + (size_t)r0 * H_DIM + col)       = make_float2(o[0], o[1]);
        *(float2*)(out + (size_t)(r0 + 8) * H_DIM + col) = make_float2(o[2], o[3]);
    }
}

// ---------------- launch ------------------------------------------------------
extern "C" void kernel_launch(void* const* d_in, const int* in_sizes, int n_in,
                              void* d_out, int out_size) {
    const float* x         = (const float*)d_in[0];
    const float* delta     = (const float*)d_in[1];
    const float* h         = (const float*)d_in[2];
    const float* weight_ih = (const float*)d_in[3];
    const float* weight_hh = (const float*)d_in[4];
    const float* bias_ih   = (const float*)d_in[5];
    const float* bias_hh   = (const float*)d_in[6];
    const float* w_gamma   = (const float*)d_in[7];
    const float* b_gamma   = (const float*)d_in[8];
    float* out = (float*)d_out;

    __half* dx;   cudaGetSymbolAddress((void**)&dx,   g_x16);
    __half* dwih; cudaGetSymbolAddress((void**)&dwih, g_wih);
    __half* dwhh; cudaGetSymbolAddress((void**)&dwhh, g_whh);

    cudaFuncSetAttribute(grud_mma_kernel,
                         cudaFuncAttributeMaxDynamicSharedMemorySize, SMEM_ALLOC);

    const int T = 256;
    { int tot = BATCH * IP / 4;  convert_pad4<<<(tot + T - 1) / T, T>>>(x, nullptr, dx, BATCH, I_DIM, IP); }
    { int tot = G3H * IP / 4;    convert_pad4<<<(tot + T - 1) / T, T>>>(weight_ih, bias_ih, dwih, G3H, I_DIM, IP); }
    { int tot = G3H * HPAD / 4;  convert_pad4<<<(tot + T - 1) / T, T>>>(weight_hh, bias_hh, dwhh, G3H, H_DIM, HPAD); }
    gamma_h_kernel<<<BATCH / GH_ROWS, 256>>>(delta, h, w_gamma, b_gamma);

    dim3 grid(BATCH / BM, H_DIM / BN);   // (64, 32)
    grud_mma_kernel<<<grid, 256, SMEM_ALLOC>>>(out);
}

// round 7
// speedup vs baseline: 1.6489x; 1.0226x over previous
#include <cuda_runtime.h>
#include <cuda_fp16.h>
#include <cstdint>

// ---------------- problem constants ------------------------------------------
#define BATCH 8192
#define I_DIM 512
#define H_DIM 1024
#define D_DIM 8
#define G3H   3072
#define IP    576            // I + 64 pad (bias column at k=512)
#define HPAD  1088           // H + 64 pad (bias/ones column at k=1024)

// ---------------- GEMM tiling ------------------------------------------------
#define BM 128               // batch rows per CTA
#define BN 64                // hidden cols per CTA (per gate; 3 gates computed)
#define KC 64                // halves per K-chunk
#define NCHUNK1 9            // 576/64   (x @ W_ih^T)
#define NCHUNKS 26           // + 1088/64 (h' @ W_hh^T)
#define NSTAGE 4
#define SPITCH 144           // bytes per SMEM row (64 halves + 8 pad) -> conflict-free
#define SROWS (BM + 3 * BN)  // 128 A rows + 192 B rows = 320
#define STAGE_BYTES (SROWS * SPITCH)            // 46080
#define SMEM_ALLOC (NSTAGE * STAGE_BYTES + 256) // ~184KB, 1 CTA/SM
#define NTHREADS 512

// ---------------- device scratch ---------------------------------------------
__device__ __half g_x16[BATCH * IP];
__device__ __half g_h16[BATCH * HPAD];
__device__ __half g_wih[G3H * IP];
__device__ __half g_whh[G3H * HPAD];

// ---------------- PTX helpers ------------------------------------------------
__device__ __forceinline__ uint32_t smem_u32(const void* p) {
    uint32_t a;
    asm("{ .reg .u64 t; cvta.to.shared.u64 t, %1; cvt.u32.u64 %0, t; }"
        : "=r"(a) : "l"(p));
    return a;
}
__device__ __forceinline__ void cp16(uint32_t dst, const void* src) {
    asm volatile("cp.async.cg.shared.global [%0], [%1], 16;" :: "r"(dst), "l"(src));
}
#define CP_COMMIT() asm volatile("cp.async.commit_group;" ::: "memory")
#define CP_WAIT(n)  asm volatile("cp.async.wait_group %0;" :: "n"(n) : "memory")
#define LDSM4(r0, r1, r2, r3, addr) \
    asm volatile("ldmatrix.sync.aligned.m8n8.x4.shared.b16 {%0,%1,%2,%3}, [%4];" \
        : "=r"(r0), "=r"(r1), "=r"(r2), "=r"(r3) : "r"(addr))

// ---------------- fused prep kernel ------------------------------------------
// blocks [0, 1024)      : gamma_h, 8 batch rows per block, w_gamma in registers
// blocks [1024, 2048)   : grid-stride fp32->fp16 converts with pad columns
#define GH_BLOCKS 1024
#define GH_ROWS 8
#define CV_BLOCKS 1024
#define PREP_BLOCKS (GH_BLOCKS + CV_BLOCKS)

__global__ void __launch_bounds__(256)
prep_kernel(const float* __restrict__ x,
            const float* __restrict__ delta,
            const float* __restrict__ h,
            const float* __restrict__ wih,
            const float* __restrict__ whh,
            const float* __restrict__ b_ih,
            const float* __restrict__ b_hh,
            const float* __restrict__ wg,
            const float* __restrict__ bg) {
    const int bid = blockIdx.x, t = threadIdx.x;
    if (bid < GH_BLOCKS) {
        // ---- gamma_h: h' = exp(-relu(delta @ Wg^T + bg)) * h ----
        const int j0 = t * 4;
        float w[4][8], b4[4];
#pragma unroll
        for (int k = 0; k < 4; k++) {
            const float4* w4 = reinterpret_cast<const float4*>(wg + (size_t)(j0 + k) * D_DIM);
            float4 lo = w4[0], hi = w4[1];
            w[k][0] = lo.x; w[k][1] = lo.y; w[k][2] = lo.z; w[k][3] = lo.w;
            w[k][4] = hi.x; w[k][5] = hi.y; w[k][6] = hi.z; w[k][7] = hi.w;
            b4[k] = bg[j0 + k];
        }
        const int r0 = bid * GH_ROWS;
#pragma unroll
        for (int b = r0; b < r0 + GH_ROWS; b++) {
            const float4* d4 = reinterpret_cast<const float4*>(delta + (size_t)b * D_DIM);
            float4 a0 = d4[0], a1 = d4[1];
            float4 hv = *reinterpret_cast<const float4*>(h + (size_t)b * H_DIM + j0);
            __half o4[4];
#pragma unroll
            for (int k = 0; k < 4; k++) {
                float s = a0.x * w[k][0] + a0.y * w[k][1] + a0.z * w[k][2] + a0.w * w[k][3]
                        + a1.x * w[k][4] + a1.y * w[k][5] + a1.z * w[k][6] + a1.w * w[k][7]
                        + b4[k];
                float g = __expf(-fmaxf(s, 0.0f));
                o4[k] = __float2half(g * (&hv.x)[k]);
            }
            *reinterpret_cast<uint2*>(g_h16 + (size_t)b * HPAD + j0) =
                *reinterpret_cast<uint2*>(o4);
            if (t < 16) {                        // pad cols 1024..1087
                int j = 1024 + t * 4;
                __half p4[4];
#pragma unroll
                for (int k = 0; k < 4; k++)
                    p4[k] = __float2half((j + k) == 1024 ? 1.0f : 0.0f);
                *reinterpret_cast<uint2*>(g_h16 + (size_t)b * HPAD + j) =
                    *reinterpret_cast<uint2*>(p4);
            }
        }
    } else {
        // ---- converts: x -> g_x16, W_ih -> g_wih, W_hh -> g_whh (4 halves/unit)
        const int n_x   = BATCH * IP / 4;
        const int n_wih = G3H * IP / 4;
        const int n_whh = G3H * HPAD / 4;
        const int total = n_x + n_wih + n_whh;
        const int start = (bid - GH_BLOCKS) * 256 + t;
        const int stride = CV_BLOCKS * 256;
        for (int u = start; u < total; u += stride) {
            const float* src; const float* bias; __half* dst; int sc, dc, v;
            if (u < n_x)               { v = u;                 src = x;   bias = nullptr; dst = g_x16; sc = I_DIM; dc = IP; }
            else if (u < n_x + n_wih)  { v = u - n_x;           src = wih; bias = b_ih;    dst = g_wih; sc = I_DIM; dc = IP; }
            else                       { v = u - n_x - n_wih;   src = whh; bias = b_hh;    dst = g_whh; sc = H_DIM; dc = HPAD; }
            int q = dc >> 2;
            int r = v / q, c0 = (v - r * q) << 2;
            float vv[4];
            if (c0 + 3 < sc) {
                float4 f = *reinterpret_cast<const float4*>(src + (size_t)r * sc + c0);
                vv[0] = f.x; vv[1] = f.y; vv[2] = f.z; vv[3] = f.w;
            } else {
#pragma unroll
                for (int k = 0; k < 4; k++) {
                    int c = c0 + k;
                    vv[k] = (c < sc) ? src[(size_t)r * sc + c]
                                     : ((c == sc) ? (bias ? bias[r] : 1.0f) : 0.0f);
                }
            }
            __half h4[4];
#pragma unroll
            for (int k = 0; k < 4; k++) h4[k] = __float2half(vv[k]);
            *reinterpret_cast<uint2*>(dst + (size_t)r * dc + c0) =
                *reinterpret_cast<uint2*>(h4);
        }
    }
}

// ---------------- chunk loader (cp.async, 2560 x 16B = 5 x 512) --------------
__device__ __forceinline__ void load_chunk(uint32_t stage_sb, int c,
                                           int bm, int jb, int tid) {
    const __half* A; const __half* B; int ld_; int kc;
    if (c < NCHUNK1) { A = g_x16; B = g_wih; ld_ = IP;   kc = c * KC; }
    else             { A = g_h16; B = g_whh; ld_ = HPAD; kc = (c - NCHUNK1) * KC; }
#pragma unroll
    for (int i = 0; i < 5; i++) {
        int u = tid + i * NTHREADS;              // 0..2559
        int row = u >> 3, cc = u & 7;            // 8 x 16B per 128B row
        const __half* src;
        if (row < BM) {
            src = A + (size_t)(bm + row) * ld_ + kc + cc * 8;
        } else {
            int rr = row - BM;                   // 0..191
            int g = rr >> 6, n = rr & 63;
            src = B + (size_t)(jb + n + g * H_DIM) * ld_ + kc + cc * 8;
        }
        cp16(stage_sb + (uint32_t)(row * SPITCH + cc * 16), src);
    }
    CP_COMMIT();
}

// ---------------- per-chunk MMA: ldmatrix-fed, 4 k-steps, 3 gates ------------
// acc slots: 0 = r_pre (both phases), 1 = z_pre (both), 2 = i_n, 3 = h_n
template <int SN>
__device__ __forceinline__ void mma_chunk(float (&acc)[4][4][4],
                                          uint32_t stage_sb,
                                          uint32_t aoff, uint32_t boff) {
#pragma unroll
    for (int ks = 0; ks < 4; ks++) {
        const uint32_t kb = ks * 32;             // k0*2 bytes
        uint32_t a0, a1, a2, a3;
        LDSM4(a0, a1, a2, a3, stage_sb + aoff + kb);
#pragma unroll
        for (int g = 0; g < 3; g++) {
            const int slot = (g == 0) ? 0 : (g == 1) ? 1 : SN;
#pragma unroll
            for (int q = 0; q < 2; q++) {        // warp's 32-col half, 16 at a time
                uint32_t b0, b1, b2, b3;
                LDSM4(b0, b1, b2, b3,
                      stage_sb + boff + (uint32_t)((g * 64 + q * 16) * SPITCH) + kb);
                asm volatile(
                    "mma.sync.aligned.m16n8k16.row.col.f32.f16.f16.f32 "
                    "{%0,%1,%2,%3}, {%4,%5,%6,%7}, {%8,%9}, {%0,%1,%2,%3};"
                    : "+f"(acc[slot][q * 2][0]), "+f"(acc[slot][q * 2][1]),
                      "+f"(acc[slot][q * 2][2]), "+f"(acc[slot][q * 2][3])
                    : "r"(a0), "r"(a1), "r"(a2), "r"(a3), "r"(b0), "r"(b1));
                asm volatile(
                    "mma.sync.aligned.m16n8k16.row.col.f32.f16.f16.f32 "
                    "{%0,%1,%2,%3}, {%4,%5,%6,%7}, {%8,%9}, {%0,%1,%2,%3};"
                    : "+f"(acc[slot][q * 2 + 1][0]), "+f"(acc[slot][q * 2 + 1][1]),
                      "+f"(acc[slot][q * 2 + 1][2]), "+f"(acc[slot][q * 2 + 1][3])
                    : "r"(a0), "r"(a1), "r"(a2), "r"(a3), "r"(b2), "r"(b3));
            }
        }
    }
}

// ---------------- main GEMM + GRU epilogue -----------------------------------
// 16 warps: (wid & 7) -> 16-row strip of BM, (wid >> 3) -> 32-col half of BN
__global__ void __launch_bounds__(NTHREADS)
grud_mma_kernel(float* __restrict__ out) {
    extern __shared__ char smem_raw[];
    const uint32_t sb = (smem_u32(smem_raw) + 127) & ~127u;

    const int tid = threadIdx.x;
    const int wid = tid >> 5, lid = tid & 31;
    const int gid = lid >> 2, tig = lid & 3;      // groupID / thread-in-group
    const int wrow = (wid & 7) * 16;              // row strip
    const int nhalf = (wid >> 3) * 32;            // col half
    const int bm = blockIdx.x * BM, jb = blockIdx.y * BN;

    // ldmatrix per-lane offsets
    const int t8 = lid >> 3, ri = lid & 7;
    // A x4 tiles: {rows@k0, rows+8@k0, rows@k0+8, rows+8@k0+8}
    const uint32_t aoff = (uint32_t)((wrow + (t8 & 1) * 8 + ri) * SPITCH + (t8 >> 1) * 16);
    // B x4 tiles: {n0-7@k0, n0-7@k0+8, n8-15@k0, n8-15@k0+8}
    const uint32_t boff = (uint32_t)((BM + nhalf + (t8 >> 1) * 8 + ri) * SPITCH + (t8 & 1) * 16);

    float acc[4][4][4];
#pragma unroll
    for (int s = 0; s < 4; s++)
#pragma unroll
        for (int n = 0; n < 4; n++)
#pragma unroll
            for (int e = 0; e < 4; e++) acc[s][n][e] = 0.0f;

    // prologue: fill NSTAGE-1 stages
    for (int c = 0; c < NSTAGE - 1; c++)
        load_chunk(sb + c * STAGE_BYTES, c, bm, jb, tid);

#pragma unroll 1
    for (int c = 0; c < NCHUNKS; c++) {
        const int st = c & 3;
        if (c < NCHUNKS - 2)       CP_WAIT(2);   // chunk c's loads complete
        else if (c == NCHUNKS - 2) CP_WAIT(1);
        else                       CP_WAIT(0);
        __syncthreads();                          // also: everyone done with c-1's stage

        if (c + NSTAGE - 1 < NCHUNKS)             // load into stage consumed at iter c-1
            load_chunk(sb + ((c + NSTAGE - 1) & 3) * STAGE_BYTES,
                       c + NSTAGE - 1, bm, jb, tid);

        const uint32_t stage_sb = sb + st * STAGE_BYTES;
        if (c < NCHUNK1) mma_chunk<2>(acc, stage_sb, aoff, boff);
        else             mma_chunk<3>(acc, stage_sb, aoff, boff);
    }

    // ---- epilogue: GRU math straight from registers -------------------------
    const int r0 = bm + wrow + gid;               // rows r0 and r0+8
#pragma unroll
    for (int n = 0; n < 4; n++) {
        const int col = jb + nhalf + n * 8 + tig * 2;
        __half2 ha = *(const __half2*)(g_h16 + (size_t)r0 * HPAD + col);
        __half2 hb = *(const __half2*)(g_h16 + (size_t)(r0 + 8) * HPAD + col);
        float hq[4] = { __half2float(ha.x), __half2float(ha.y),
                        __half2float(hb.x), __half2float(hb.y) };
        float o[4];
#pragma unroll
        for (int e = 0; e < 4; e++) {
            float r  = 1.0f / (1.0f + __expf(-acc[0][n][e]));
            float z  = 1.0f / (1.0f + __expf(-acc[1][n][e]));
            float na = acc[2][n][e] + r * acc[3][n][e];
            float nn = 2.0f / (1.0f + __expf(-2.0f * na)) - 1.0f;   // tanh
            o[e] = nn + z * (hq[e] - nn);
        }
        *(float2*)(out + (size_t)r0 * H_DIM + col)       = make_float2(o[0], o[1]);
        *(float2*)(out + (size_t)(r0 + 8) * H_DIM + col) = make_float2(o[2], o[3]);
    }
}

// ---------------- launch ------------------------------------------------------
extern "C" void kernel_launch(void* const* d_in, const int* in_sizes, int n_in,
                              void* d_out, int out_size) {
    const float* x         = (const float*)d_in[0];
    const float* delta     = (const float*)d_in[1];
    const float* h         = (const float*)d_in[2];
    const float* weight_ih = (const float*)d_in[3];
    const float* weight_hh = (const float*)d_in[4];
    const float* bias_ih   = (const float*)d_in[5];
    const float* bias_hh   = (const float*)d_in[6];
    const float* w_gamma   = (const float*)d_in[7];
    const float* b_gamma   = (const float*)d_in[8];
    float* out = (float*)d_out;

    cudaFuncSetAttribute(grud_mma_kernel,
                         cudaFuncAttributeMaxDynamicSharedMemorySize, SMEM_ALLOC);

    prep_kernel<<<PREP_BLOCKS, 256>>>(x, delta, h, weight_ih, weight_hh,
                                      bias_ih, bias_hh, w_gamma, b_gamma);

    dim3 grid(BATCH / BM, H_DIM / BN);   // (64, 16)
    grud_mma_kernel<<<grid, NTHREADS, SMEM_ALLOC>>>(out);
}

// round 8
// speedup vs baseline: 1.8128x; 1.0994x over previous
#include <cuda_runtime.h>
#include <cuda_fp16.h>
#include <cstdint>

// ---------------- problem constants ------------------------------------------
#define BATCH 8192
#define I_DIM 512
#define H_DIM 1024
#define D_DIM 8
#define G3H   3072
#define IP    576            // I + 64 pad (bias column at k=512)
#define HPAD  1088           // H + 64 pad (bias/ones column at k=1024)

// ---------------- GEMM tiling ------------------------------------------------
#define BM 128               // batch rows per CTA
#define BN 64                // hidden cols per CTA (per gate; 3 gates computed)
#define KC 64                // halves per K-chunk
#define NCHUNK1 9            // 576/64   (x @ W_ih^T)
#define NCHUNKS 26           // + 1088/64 (h' @ W_hh^T)
#define NSTAGE 4
#define SPITCH 144           // bytes per SMEM row (64 halves + 8 pad) -> conflict-free
#define SROWS (BM + 3 * BN)  // 128 A rows + 192 B rows = 320
#define STAGE_BYTES (SROWS * SPITCH)            // 46080
#define SMEM_ALLOC (NSTAGE * STAGE_BYTES + 256) // ~184KB, 1 CTA/SM
#define NTHREADS 512

// ---------------- device scratch ---------------------------------------------
__device__ __half g_x16[BATCH * IP];
__device__ __half g_h16[BATCH * HPAD];
__device__ __half g_wih[G3H * IP];
__device__ __half g_whh[G3H * HPAD];

// ---------------- PTX helpers ------------------------------------------------
__device__ __forceinline__ uint32_t smem_u32(const void* p) {
    uint32_t a;
    asm("{ .reg .u64 t; cvta.to.shared.u64 t, %1; cvt.u32.u64 %0, t; }"
        : "=r"(a) : "l"(p));
    return a;
}
__device__ __forceinline__ void cp16(uint32_t dst, const void* src) {
    asm volatile("cp.async.cg.shared.global [%0], [%1], 16;" :: "r"(dst), "l"(src));
}
#define CP_COMMIT() asm volatile("cp.async.commit_group;" ::: "memory")
#define CP_WAIT(n)  asm volatile("cp.async.wait_group %0;" :: "n"(n) : "memory")
#define LDSM4(r0, r1, r2, r3, addr) \
    asm volatile("ldmatrix.sync.aligned.m8n8.x4.shared.b16 {%0,%1,%2,%3}, [%4];" \
        : "=r"(r0), "=r"(r1), "=r"(r2), "=r"(r3) : "r"(addr))
#define MMA16816(acc, a0, a1, a2, a3, b0, b1) \
    asm volatile( \
        "mma.sync.aligned.m16n8k16.row.col.f32.f16.f16.f32 " \
        "{%0,%1,%2,%3}, {%4,%5,%6,%7}, {%8,%9}, {%0,%1,%2,%3};" \
        : "+f"((acc)[0]), "+f"((acc)[1]), "+f"((acc)[2]), "+f"((acc)[3]) \
        : "r"(a0), "r"(a1), "r"(a2), "r"(a3), "r"(b0), "r"(b1))

// ---------------- fused prep kernel ------------------------------------------
// blocks [0, 1024)      : gamma_h, 8 batch rows per block, w_gamma in registers
// blocks [1024, 2048)   : grid-stride fp32->fp16 converts with pad columns
#define GH_BLOCKS 1024
#define GH_ROWS 8
#define CV_BLOCKS 1024
#define PREP_BLOCKS (GH_BLOCKS + CV_BLOCKS)

__global__ void __launch_bounds__(256)
prep_kernel(const float* __restrict__ x,
            const float* __restrict__ delta,
            const float* __restrict__ h,
            const float* __restrict__ wih,
            const float* __restrict__ whh,
            const float* __restrict__ b_ih,
            const float* __restrict__ b_hh,
            const float* __restrict__ wg,
            const float* __restrict__ bg) {
    const int bid = blockIdx.x, t = threadIdx.x;
    if (bid < GH_BLOCKS) {
        // ---- gamma_h: h' = exp(-relu(delta @ Wg^T + bg)) * h ----
        const int j0 = t * 4;
        float w[4][8], b4[4];
#pragma unroll
        for (int k = 0; k < 4; k++) {
            const float4* w4 = reinterpret_cast<const float4*>(wg + (size_t)(j0 + k) * D_DIM);
            float4 lo = w4[0], hi = w4[1];
            w[k][0] = lo.x; w[k][1] = lo.y; w[k][2] = lo.z; w[k][3] = lo.w;
            w[k][4] = hi.x; w[k][5] = hi.y; w[k][6] = hi.z; w[k][7] = hi.w;
            b4[k] = bg[j0 + k];
        }
        const int r0 = bid * GH_ROWS;
#pragma unroll
        for (int b = r0; b < r0 + GH_ROWS; b++) {
            const float4* d4 = reinterpret_cast<const float4*>(delta + (size_t)b * D_DIM);
            float4 a0 = d4[0], a1 = d4[1];
            float4 hv = *reinterpret_cast<const float4*>(h + (size_t)b * H_DIM + j0);
            __half o4[4];
#pragma unroll
            for (int k = 0; k < 4; k++) {
                float s = a0.x * w[k][0] + a0.y * w[k][1] + a0.z * w[k][2] + a0.w * w[k][3]
                        + a1.x * w[k][4] + a1.y * w[k][5] + a1.z * w[k][6] + a1.w * w[k][7]
                        + b4[k];
                float g = __expf(-fmaxf(s, 0.0f));
                o4[k] = __float2half(g * (&hv.x)[k]);
            }
            *reinterpret_cast<uint2*>(g_h16 + (size_t)b * HPAD + j0) =
                *reinterpret_cast<uint2*>(o4);
            if (t < 16) {                        // pad cols 1024..1087
                int j = 1024 + t * 4;
                __half p4[4];
#pragma unroll
                for (int k = 0; k < 4; k++)
                    p4[k] = __float2half((j + k) == 1024 ? 1.0f : 0.0f);
                *reinterpret_cast<uint2*>(g_h16 + (size_t)b * HPAD + j) =
                    *reinterpret_cast<uint2*>(p4);
            }
        }
    } else {
        // ---- converts: x -> g_x16, W_ih -> g_wih, W_hh -> g_whh (4 halves/unit)
        const int n_x   = BATCH * IP / 4;
        const int n_wih = G3H * IP / 4;
        const int n_whh = G3H * HPAD / 4;
        const int total = n_x + n_wih + n_whh;
        const int start = (bid - GH_BLOCKS) * 256 + t;
        const int stride = CV_BLOCKS * 256;
        for (int u = start; u < total; u += stride) {
            const float* src; const float* bias; __half* dst; int sc, dc, v;
            if (u < n_x)               { v = u;                 src = x;   bias = nullptr; dst = g_x16; sc = I_DIM; dc = IP; }
            else if (u < n_x + n_wih)  { v = u - n_x;           src = wih; bias = b_ih;    dst = g_wih; sc = I_DIM; dc = IP; }
            else                       { v = u - n_x - n_wih;   src = whh; bias = b_hh;    dst = g_whh; sc = H_DIM; dc = HPAD; }
            int q = dc >> 2;
            int r = v / q, c0 = (v - r * q) << 2;
            float vv[4];
            if (c0 + 3 < sc) {
                float4 f = *reinterpret_cast<const float4*>(src + (size_t)r * sc + c0);
                vv[0] = f.x; vv[1] = f.y; vv[2] = f.z; vv[3] = f.w;
            } else {
#pragma unroll
                for (int k = 0; k < 4; k++) {
                    int c = c0 + k;
                    vv[k] = (c < sc) ? src[(size_t)r * sc + c]
                                     : ((c == sc) ? (bias ? bias[r] : 1.0f) : 0.0f);
                }
            }
            __half h4[4];
#pragma unroll
            for (int k = 0; k < 4; k++) h4[k] = __float2half(vv[k]);
            *reinterpret_cast<uint2*>(dst + (size_t)r * dc + c0) =
                *reinterpret_cast<uint2*>(h4);
        }
    }
}

// ---------------- chunk loader (cp.async, 2560 x 16B = 5 x 512) --------------
__device__ __forceinline__ void load_chunk(uint32_t stage_sb, int c,
                                           int bm, int jb, int tid) {
    const __half* A; const __half* B; int ld_; int kc;
    if (c < NCHUNK1) { A = g_x16; B = g_wih; ld_ = IP;   kc = c * KC; }
    else             { A = g_h16; B = g_whh; ld_ = HPAD; kc = (c - NCHUNK1) * KC; }
#pragma unroll
    for (int i = 0; i < 5; i++) {
        int u = tid + i * NTHREADS;              // 0..2559
        int row = u >> 3, cc = u & 7;            // 8 x 16B per 128B row
        const __half* src;
        if (row < BM) {
            src = A + (size_t)(bm + row) * ld_ + kc + cc * 8;
        } else {
            int rr = row - BM;                   // 0..191
            int g = rr >> 6, n = rr & 63;
            src = B + (size_t)(jb + n + g * H_DIM) * ld_ + kc + cc * 8;
        }
        cp16(stage_sb + (uint32_t)(row * SPITCH + cc * 16), src);
    }
    CP_COMMIT();
}

// ---------------- per-chunk MMA: M=32/warp, N=16/warp per gate ---------------
// acc slots: 0 = r_pre (both phases), 1 = z_pre (both), 2 = i_n, 3 = h_n
// Each B ldmatrix.x4 (16 cols x k16) now feeds 4 MMAs (2 row sub-tiles).
template <int SN>
__device__ __forceinline__ void mma_chunk(float (&acc)[4][2][2][4],
                                          uint32_t stage_sb,
                                          uint32_t aoff0, uint32_t aoff1,
                                          uint32_t boff) {
#pragma unroll
    for (int ks = 0; ks < 4; ks++) {
        const uint32_t kb = ks * 32;             // k0*2 bytes
        uint32_t a0[4], a1[4];
        LDSM4(a0[0], a0[1], a0[2], a0[3], stage_sb + aoff0 + kb);  // rows wrow..+15
        LDSM4(a1[0], a1[1], a1[2], a1[3], stage_sb + aoff1 + kb);  // rows wrow+16..+31
#pragma unroll
        for (int g = 0; g < 3; g++) {
            const int slot = (g == 0) ? 0 : (g == 1) ? 1 : SN;
            uint32_t b0, b1, b2, b3;
            LDSM4(b0, b1, b2, b3,
                  stage_sb + boff + (uint32_t)(g * 64 * SPITCH) + kb);
            MMA16816(acc[slot][0][0], a0[0], a0[1], a0[2], a0[3], b0, b1);
            MMA16816(acc[slot][0][1], a0[0], a0[1], a0[2], a0[3], b2, b3);
            MMA16816(acc[slot][1][0], a1[0], a1[1], a1[2], a1[3], b0, b1);
            MMA16816(acc[slot][1][1], a1[0], a1[1], a1[2], a1[3], b2, b3);
        }
    }
}

// ---------------- main GEMM + GRU epilogue -----------------------------------
// 16 warps: (wid & 3) -> 32-row strip of BM, (wid >> 2) -> 16-col quarter of BN
__global__ void __launch_bounds__(NTHREADS)
grud_mma_kernel(float* __restrict__ out) {
    extern __shared__ char smem_raw[];
    const uint32_t sb = (smem_u32(smem_raw) + 127) & ~127u;

    const int tid = threadIdx.x;
    const int wid = tid >> 5, lid = tid & 31;
    const int gid = lid >> 2, tig = lid & 3;      // groupID / thread-in-group
    const int wrow = (wid & 3) * 32;              // 32-row strip
    const int nq   = (wid >> 2) * 16;             // 16-col quarter
    const int bm = blockIdx.x * BM, jb = blockIdx.y * BN;

    // ldmatrix per-lane offsets
    const int t8 = lid >> 3, ri = lid & 7;
    // A x4 tiles: {rows@k0, rows+8@k0, rows@k0+8, rows+8@k0+8}
    const uint32_t aoff0 = (uint32_t)((wrow +      (t8 & 1) * 8 + ri) * SPITCH + (t8 >> 1) * 16);
    const uint32_t aoff1 = (uint32_t)((wrow + 16 + (t8 & 1) * 8 + ri) * SPITCH + (t8 >> 1) * 16);
    // B x4 tiles: {n0-7@k0, n0-7@k0+8, n8-15@k0, n8-15@k0+8}
    const uint32_t boff = (uint32_t)((BM + nq + (t8 >> 1) * 8 + ri) * SPITCH + (t8 & 1) * 16);

    float acc[4][2][2][4];
#pragma unroll
    for (int s = 0; s < 4; s++)
#pragma unroll
        for (int m = 0; m < 2; m++)
#pragma unroll
            for (int n = 0; n < 2; n++)
#pragma unroll
                for (int e = 0; e < 4; e++) acc[s][m][n][e] = 0.0f;

    // prologue: fill NSTAGE-1 stages
    for (int c = 0; c < NSTAGE - 1; c++)
        load_chunk(sb + c * STAGE_BYTES, c, bm, jb, tid);

#pragma unroll 1
    for (int c = 0; c < NCHUNKS; c++) {
        const int st = c & 3;
        if (c < NCHUNKS - 2)       CP_WAIT(2);   // chunk c's loads complete
        else if (c == NCHUNKS - 2) CP_WAIT(1);
        else                       CP_WAIT(0);
        __syncthreads();                          // also: everyone done with c-1's stage

        if (c + NSTAGE - 1 < NCHUNKS)             // load into stage consumed at iter c-1
            load_chunk(sb + ((c + NSTAGE - 1) & 3) * STAGE_BYTES,
                       c + NSTAGE - 1, bm, jb, tid);

        const uint32_t stage_sb = sb + st * STAGE_BYTES;
        if (c < NCHUNK1) mma_chunk<2>(acc, stage_sb, aoff0, aoff1, boff);
        else             mma_chunk<3>(acc, stage_sb, aoff0, aoff1, boff);
    }

    // ---- epilogue: GRU math straight from registers -------------------------
#pragma unroll
    for (int m = 0; m < 2; m++) {
        const int r0 = bm + wrow + m * 16 + gid;  // rows r0 and r0+8
#pragma unroll
        for (int n = 0; n < 2; n++) {
            const int col = jb + nq + n * 8 + tig * 2;
            __half2 ha = *(const __half2*)(g_h16 + (size_t)r0 * HPAD + col);
            __half2 hb = *(const __half2*)(g_h16 + (size_t)(r0 + 8) * HPAD + col);
            float hq[4] = { __half2float(ha.x), __half2float(ha.y),
                            __half2float(hb.x), __half2float(hb.y) };
            float o[4];
#pragma unroll
            for (int e = 0; e < 4; e++) {
                float r  = 1.0f / (1.0f + __expf(-acc[0][m][n][e]));
                float z  = 1.0f / (1.0f + __expf(-acc[1][m][n][e]));
                float na = acc[2][m][n][e] + r * acc[3][m][n][e];
                float nn = 2.0f / (1.0f + __expf(-2.0f * na)) - 1.0f;   // tanh
                o[e] = nn + z * (hq[e] - nn);
            }
            *(float2*)(out + (size_t)r0 * H_DIM + col)       = make_float2(o[0], o[1]);
            *(float2*)(out + (size_t)(r0 + 8) * H_DIM + col) = make_float2(o[2], o[3]);
        }
    }
}

// ---------------- launch ------------------------------------------------------
extern "C" void kernel_launch(void* const* d_in, const int* in_sizes, int n_in,
                              void* d_out, int out_size) {
    const float* x         = (const float*)d_in[0];
    const float* delta     = (const float*)d_in[1];
    const float* h         = (const float*)d_in[2];
    const float* weight_ih = (const float*)d_in[3];
    const float* weight_hh = (const float*)d_in[4];
    const float* bias_ih   = (const float*)d_in[5];
    const float* bias_hh   = (const float*)d_in[6];
    const float* w_gamma   = (const float*)d_in[7];
    const float* b_gamma   = (const float*)d_in[8];
    float* out = (float*)d_out;

    cudaFuncSetAttribute(grud_mma_kernel,
                         cudaFuncAttributeMaxDynamicSharedMemorySize, SMEM_ALLOC);

    prep_kernel<<<PREP_BLOCKS, 256>>>(x, delta, h, weight_ih, weight_hh,
                                      bias_ih, bias_hh, w_gamma, b_gamma);

    dim3 grid(BATCH / BM, H_DIM / BN);   // (64, 16)
    grud_mma_kernel<<<grid, NTHREADS, SMEM_ALLOC>>>(out);
}

// round 9
// speedup vs baseline: 1.8130x; 1.0001x over previous
#include <cuda_runtime.h>
#include <cuda_fp16.h>
#include <cstdint>

// ---------------- problem constants ------------------------------------------
#define BATCH 8192
#define I_DIM 512
#define H_DIM 1024
#define D_DIM 8
#define G3H   3072
#define IP    576            // I + 64 pad (bias column at k=512)
#define HPAD  1088           // H + 64 pad (bias/ones column at k=1024)

// ---------------- GEMM tiling ------------------------------------------------
#define BM 128               // batch rows per CTA
#define BN 64                // hidden cols per CTA (per gate; 3 gates computed)
#define KC 64                // halves per K-chunk
#define NCHUNK1 9            // 576/64   (x @ W_ih^T)
#define NCHUNKS 26           // + 1088/64 (h' @ W_hh^T)
#define NSTAGE 4
#define SPITCH 144           // bytes per SMEM row (64 halves + 8 pad) -> conflict-free
#define SROWS (BM + 3 * BN)  // 128 A rows + 192 B rows = 320
#define STAGE_BYTES (SROWS * SPITCH)            // 46080
#define SMEM_ALLOC (NSTAGE * STAGE_BYTES + 256) // ~184KB, 1 CTA/SM
#define NTHREADS 512

// ---------------- device scratch ---------------------------------------------
__device__ __half g_x16[BATCH * IP];
__device__ __half g_h16[BATCH * HPAD];
__device__ __half g_wih[G3H * IP];
__device__ __half g_whh[G3H * HPAD];

// ---------------- PTX helpers ------------------------------------------------
__device__ __forceinline__ uint32_t smem_u32(const void* p) {
    uint32_t a;
    asm("{ .reg .u64 t; cvta.to.shared.u64 t, %1; cvt.u32.u64 %0, t; }"
        : "=r"(a) : "l"(p));
    return a;
}
__device__ __forceinline__ void cp16(uint32_t dst, const void* src) {
    asm volatile("cp.async.cg.shared.global [%0], [%1], 16;" :: "r"(dst), "l"(src));
}
#define CP_COMMIT() asm volatile("cp.async.commit_group;" ::: "memory")
#define CP_WAIT(n)  asm volatile("cp.async.wait_group %0;" :: "n"(n) : "memory")
#define LDSM4(r0, r1, r2, r3, addr) \
    asm volatile("ldmatrix.sync.aligned.m8n8.x4.shared.b16 {%0,%1,%2,%3}, [%4];" \
        : "=r"(r0), "=r"(r1), "=r"(r2), "=r"(r3) : "r"(addr))
#define MMA16816(acc, a0, a1, a2, a3, b0, b1) \
    asm volatile( \
        "mma.sync.aligned.m16n8k16.row.col.f32.f16.f16.f32 " \
        "{%0,%1,%2,%3}, {%4,%5,%6,%7}, {%8,%9}, {%0,%1,%2,%3};" \
        : "+f"((acc)[0]), "+f"((acc)[1]), "+f"((acc)[2]), "+f"((acc)[3]) \
        : "r"(a0), "r"(a1), "r"(a2), "r"(a3), "r"(b0), "r"(b1))

// ---------------- fused prep kernel ------------------------------------------
// blocks [0, 1024)      : gamma_h, 8 batch rows per block, w_gamma in registers
// blocks [1024, 2048)   : grid-stride fp32->fp16 converts with pad columns
#define GH_BLOCKS 1024
#define GH_ROWS 8
#define CV_BLOCKS 1024
#define PREP_BLOCKS (GH_BLOCKS + CV_BLOCKS)

__global__ void __launch_bounds__(256)
prep_kernel(const float* __restrict__ x,
            const float* __restrict__ delta,
            const float* __restrict__ h,
            const float* __restrict__ wih,
            const float* __restrict__ whh,
            const float* __restrict__ b_ih,
            const float* __restrict__ b_hh,
            const float* __restrict__ wg,
            const float* __restrict__ bg) {
    const int bid = blockIdx.x, t = threadIdx.x;
    if (bid < GH_BLOCKS) {
        // ---- gamma_h: h' = exp(-relu(delta @ Wg^T + bg)) * h ----
        const int j0 = t * 4;
        float w[4][8], b4[4];
#pragma unroll
        for (int k = 0; k < 4; k++) {
            const float4* w4 = reinterpret_cast<const float4*>(wg + (size_t)(j0 + k) * D_DIM);
            float4 lo = w4[0], hi = w4[1];
            w[k][0] = lo.x; w[k][1] = lo.y; w[k][2] = lo.z; w[k][3] = lo.w;
            w[k][4] = hi.x; w[k][5] = hi.y; w[k][6] = hi.z; w[k][7] = hi.w;
            b4[k] = bg[j0 + k];
        }
        const int r0 = bid * GH_ROWS;
#pragma unroll
        for (int b = r0; b < r0 + GH_ROWS; b++) {
            const float4* d4 = reinterpret_cast<const float4*>(delta + (size_t)b * D_DIM);
            float4 a0 = d4[0], a1 = d4[1];
            float4 hv = *reinterpret_cast<const float4*>(h + (size_t)b * H_DIM + j0);
            __half o4[4];
#pragma unroll
            for (int k = 0; k < 4; k++) {
                float s = a0.x * w[k][0] + a0.y * w[k][1] + a0.z * w[k][2] + a0.w * w[k][3]
                        + a1.x * w[k][4] + a1.y * w[k][5] + a1.z * w[k][6] + a1.w * w[k][7]
                        + b4[k];
                float g = __expf(-fmaxf(s, 0.0f));
                o4[k] = __float2half(g * (&hv.x)[k]);
            }
            *reinterpret_cast<uint2*>(g_h16 + (size_t)b * HPAD + j0) =
                *reinterpret_cast<uint2*>(o4);
            if (t < 16) {                        // pad cols 1024..1087
                int j = 1024 + t * 4;
                __half p4[4];
#pragma unroll
                for (int k = 0; k < 4; k++)
                    p4[k] = __float2half((j + k) == 1024 ? 1.0f : 0.0f);
                *reinterpret_cast<uint2*>(g_h16 + (size_t)b * HPAD + j) =
                    *reinterpret_cast<uint2*>(p4);
            }
        }
    } else {
        // ---- converts: x -> g_x16, W_ih -> g_wih, W_hh -> g_whh (4 halves/unit)
        const int n_x   = BATCH * IP / 4;
        const int n_wih = G3H * IP / 4;
        const int n_whh = G3H * HPAD / 4;
        const int total = n_x + n_wih + n_whh;
        const int start = (bid - GH_BLOCKS) * 256 + t;
        const int stride = CV_BLOCKS * 256;
        for (int u = start; u < total; u += stride) {
            const float* src; const float* bias; __half* dst; int sc, dc, v;
            if (u < n_x)               { v = u;                 src = x;   bias = nullptr; dst = g_x16; sc = I_DIM; dc = IP; }
            else if (u < n_x + n_wih)  { v = u - n_x;           src = wih; bias = b_ih;    dst = g_wih; sc = I_DIM; dc = IP; }
            else                       { v = u - n_x - n_wih;   src = whh; bias = b_hh;    dst = g_whh; sc = H_DIM; dc = HPAD; }
            int q = dc >> 2;
            int r = v / q, c0 = (v - r * q) << 2;
            float vv[4];
            if (c0 + 3 < sc) {
                float4 f = *reinterpret_cast<const float4*>(src + (size_t)r * sc + c0);
                vv[0] = f.x; vv[1] = f.y; vv[2] = f.z; vv[3] = f.w;
            } else {
#pragma unroll
                for (int k = 0; k < 4; k++) {
                    int c = c0 + k;
                    vv[k] = (c < sc) ? src[(size_t)r * sc + c]
                                     : ((c == sc) ? (bias ? bias[r] : 1.0f) : 0.0f);
                }
            }
            __half h4[4];
#pragma unroll
            for (int k = 0; k < 4; k++) h4[k] = __float2half(vv[k]);
            *reinterpret_cast<uint2*>(dst + (size_t)r * dc + c0) =
                *reinterpret_cast<uint2*>(h4);
        }
    }
}

// ---------------- chunk loader (cp.async, 2560 x 16B = 5 x 512) --------------
__device__ __forceinline__ void load_chunk(uint32_t stage_sb, int c,
                                           int bm, int jb, int tid) {
    const __half* A; const __half* B; int ld_; int kc;
    if (c < NCHUNK1) { A = g_x16; B = g_wih; ld_ = IP;   kc = c * KC; }
    else             { A = g_h16; B = g_whh; ld_ = HPAD; kc = (c - NCHUNK1) * KC; }
#pragma unroll
    for (int i = 0; i < 5; i++) {
        int u = tid + i * NTHREADS;              // 0..2559
        int row = u >> 3, cc = u & 7;            // 8 x 16B per 128B row
        const __half* src;
        if (row < BM) {
            src = A + (size_t)(bm + row) * ld_ + kc + cc * 8;
        } else {
            int rr = row - BM;                   // 0..191
            int g = rr >> 6, n = rr & 63;
            src = B + (size_t)(jb + n + g * H_DIM) * ld_ + kc + cc * 8;
        }
        cp16(stage_sb + (uint32_t)(row * SPITCH + cc * 16), src);
    }
    CP_COMMIT();
}

// ---------------- per-chunk MMA: software-pipelined fragments ----------------
// acc slots: 0 = r_pre (both phases), 1 = z_pre (both), 2 = i_n, 3 = h_n
// 12 stages per chunk (4 ks x 3 gates); stage i prefetches stage i+1's
// fragments BEFORE issuing its 4 MMAs, so every ldmatrix hides behind tensor
// work. A double-buffered on ks parity, B on stage parity.
template <int SN>
__device__ __forceinline__ void mma_chunk(float (&acc)[4][2][2][4],
                                          uint32_t stage_sb,
                                          uint32_t aoff0, uint32_t aoff1,
                                          uint32_t boff) {
    uint32_t a[2][2][4];   // [ks&1][m-subtile][reg]
    uint32_t b[2][4];      // [stage&1][reg]

    // preload stage 0: A(ks=0) both strips, B(g=0, ks=0)
    LDSM4(a[0][0][0], a[0][0][1], a[0][0][2], a[0][0][3], stage_sb + aoff0);
    LDSM4(a[0][1][0], a[0][1][1], a[0][1][2], a[0][1][3], stage_sb + aoff1);
    LDSM4(b[0][0], b[0][1], b[0][2], b[0][3], stage_sb + boff);

#pragma unroll
    for (int ks = 0; ks < 4; ks++) {
        const uint32_t kb = ks * 32;             // k-step byte offset
        const int ab = ks & 1;
#pragma unroll
        for (int g = 0; g < 3; g++) {
            const int bb = (ks * 3 + g) & 1;
            // ---- prefetch next stage's fragments ----
            if (g < 2) {
                LDSM4(b[bb ^ 1][0], b[bb ^ 1][1], b[bb ^ 1][2], b[bb ^ 1][3],
                      stage_sb + boff + (uint32_t)((g + 1) * 64 * SPITCH) + kb);
            } else if (ks < 3) {
                const uint32_t kb2 = kb + 32;
                LDSM4(a[ab ^ 1][0][0], a[ab ^ 1][0][1], a[ab ^ 1][0][2], a[ab ^ 1][0][3],
                      stage_sb + aoff0 + kb2);
                LDSM4(a[ab ^ 1][1][0], a[ab ^ 1][1][1], a[ab ^ 1][1][2], a[ab ^ 1][1][3],
                      stage_sb + aoff1 + kb2);
                LDSM4(b[bb ^ 1][0], b[bb ^ 1][1], b[bb ^ 1][2], b[bb ^ 1][3],
                      stage_sb + boff + kb2);
            }
            // ---- 4 MMAs with current fragments ----
            const int slot = (g == 0) ? 0 : (g == 1) ? 1 : SN;
            MMA16816(acc[slot][0][0], a[ab][0][0], a[ab][0][1], a[ab][0][2], a[ab][0][3],
                     b[bb][0], b[bb][1]);
            MMA16816(acc[slot][0][1], a[ab][0][0], a[ab][0][1], a[ab][0][2], a[ab][0][3],
                     b[bb][2], b[bb][3]);
            MMA16816(acc[slot][1][0], a[ab][1][0], a[ab][1][1], a[ab][1][2], a[ab][1][3],
                     b[bb][0], b[bb][1]);
            MMA16816(acc[slot][1][1], a[ab][1][0], a[ab][1][1], a[ab][1][2], a[ab][1][3],
                     b[bb][2], b[bb][3]);
        }
    }
}

// ---------------- main GEMM + GRU epilogue -----------------------------------
// 16 warps: (wid & 3) -> 32-row strip of BM, (wid >> 2) -> 16-col quarter of BN
__global__ void __launch_bounds__(NTHREADS)
grud_mma_kernel(float* __restrict__ out) {
    extern __shared__ char smem_raw[];
    const uint32_t sb = (smem_u32(smem_raw) + 127) & ~127u;

    const int tid = threadIdx.x;
    const int wid = tid >> 5, lid = tid & 31;
    const int gid = lid >> 2, tig = lid & 3;      // groupID / thread-in-group
    const int wrow = (wid & 3) * 32;              // 32-row strip
    const int nq   = (wid >> 2) * 16;             // 16-col quarter
    const int bm = blockIdx.x * BM, jb = blockIdx.y * BN;

    // ldmatrix per-lane offsets
    const int t8 = lid >> 3, ri = lid & 7;
    // A x4 tiles: {rows@k0, rows+8@k0, rows@k0+8, rows+8@k0+8}
    const uint32_t aoff0 = (uint32_t)((wrow +      (t8 & 1) * 8 + ri) * SPITCH + (t8 >> 1) * 16);
    const uint32_t aoff1 = (uint32_t)((wrow + 16 + (t8 & 1) * 8 + ri) * SPITCH + (t8 >> 1) * 16);
    // B x4 tiles: {n0-7@k0, n0-7@k0+8, n8-15@k0, n8-15@k0+8}
    const uint32_t boff = (uint32_t)((BM + nq + (t8 >> 1) * 8 + ri) * SPITCH + (t8 & 1) * 16);

    float acc[4][2][2][4];
#pragma unroll
    for (int s = 0; s < 4; s++)
#pragma unroll
        for (int m = 0; m < 2; m++)
#pragma unroll
            for (int n = 0; n < 2; n++)
#pragma unroll
                for (int e = 0; e < 4; e++) acc[s][m][n][e] = 0.0f;

    // prologue: fill NSTAGE-1 stages
    for (int c = 0; c < NSTAGE - 1; c++)
        load_chunk(sb + c * STAGE_BYTES, c, bm, jb, tid);

#pragma unroll 1
    for (int c = 0; c < NCHUNKS; c++) {
        const int st = c & 3;
        if (c < NCHUNKS - 2)       CP_WAIT(2);   // chunk c's loads complete
        else if (c == NCHUNKS - 2) CP_WAIT(1);
        else                       CP_WAIT(0);
        __syncthreads();                          // also: everyone done with c-1's stage

        if (c + NSTAGE - 1 < NCHUNKS)             // load into stage consumed at iter c-1
            load_chunk(sb + ((c + NSTAGE - 1) & 3) * STAGE_BYTES,
                       c + NSTAGE - 1, bm, jb, tid);

        const uint32_t stage_sb = sb + st * STAGE_BYTES;
        if (c < NCHUNK1) mma_chunk<2>(acc, stage_sb, aoff0, aoff1, boff);
        else             mma_chunk<3>(acc, stage_sb, aoff0, aoff1, boff);
    }

    // ---- epilogue: GRU math straight from registers -------------------------
#pragma unroll
    for (int m = 0; m < 2; m++) {
        const int r0 = bm + wrow + m * 16 + gid;  // rows r0 and r0+8
#pragma unroll
        for (int n = 0; n < 2; n++) {
            const int col = jb + nq + n * 8 + tig * 2;
            __half2 ha = *(const __half2*)(g_h16 + (size_t)r0 * HPAD + col);
            __half2 hb = *(const __half2*)(g_h16 + (size_t)(r0 + 8) * HPAD + col);
            float hq[4] = { __half2float(ha.x), __half2float(ha.y),
                            __half2float(hb.x), __half2float(hb.y) };
            float o[4];
#pragma unroll
            for (int e = 0; e < 4; e++) {
                float r  = 1.0f / (1.0f + __expf(-acc[0][m][n][e]));
                float z  = 1.0f / (1.0f + __expf(-acc[1][m][n][e]));
                float na = acc[2][m][n][e] + r * acc[3][m][n][e];
                float nn = 2.0f / (1.0f + __expf(-2.0f * na)) - 1.0f;   // tanh
                o[e] = nn + z * (hq[e] - nn);
            }
            *(float2*)(out + (size_t)r0 * H_DIM + col)       = make_float2(o[0], o[1]);
            *(float2*)(out + (size_t)(r0 + 8) * H_DIM + col) = make_float2(o[2], o[3]);
        }
    }
}

// ---------------- launch ------------------------------------------------------
extern "C" void kernel_launch(void* const* d_in, const int* in_sizes, int n_in,
                              void* d_out, int out_size) {
    const float* x         = (const float*)d_in[0];
    const float* delta     = (const float*)d_in[1];
    const float* h         = (const float*)d_in[2];
    const float* weight_ih = (const float*)d_in[3];
    const float* weight_hh = (const float*)d_in[4];
    const float* bias_ih   = (const float*)d_in[5];
    const float* bias_hh   = (const float*)d_in[6];
    const float* w_gamma   = (const float*)d_in[7];
    const float* b_gamma   = (const float*)d_in[8];
    float* out = (float*)d_out;

    cudaFuncSetAttribute(grud_mma_kernel,
                         cudaFuncAttributeMaxDynamicSharedMemorySize, SMEM_ALLOC);

    prep_kernel<<<PREP_BLOCKS, 256>>>(x, delta, h, weight_ih, weight_hh,
                                      bias_ih, bias_hh, w_gamma, b_gamma);

    dim3 grid(BATCH / BM, H_DIM / BN);   // (64, 16)
    grud_mma_kernel<<<grid, NTHREADS, SMEM_ALLOC>>>(out);
}